// round 16
// baseline (speedup 1.0000x reference)
#include <cuda_runtime.h>

#define HID 24
#define TPB 32
#define NSEQ 3
#define WSTRIDE 218   // u64 stride per q-block (216 payload + 2 pad) -> q-blocks on distinct bank quads

typedef unsigned long long u64;

__device__ __forceinline__ u64 pack2(float x, float y) {
    u64 r; asm("mov.b64 %0, {%1, %2};" : "=l"(r) : "f"(x), "f"(y)); return r;
}
__device__ __forceinline__ void unpack2(u64 v, float &x, float &y) {
    asm("mov.b64 {%0, %1}, %2;" : "=f"(x), "=f"(y) : "l"(v));
}
__device__ __forceinline__ u64 ffma2(u64 a, u64 b, u64 c) {
    u64 d; asm("fma.rn.f32x2 %0, %1, %2, %3;" : "=l"(d) : "l"(a), "l"(b), "l"(c)); return d;
}
__device__ __forceinline__ u64 fadd2(u64 a, u64 b) {
    u64 d; asm("add.rn.f32x2 %0, %1, %2;" : "=l"(d) : "l"(a), "l"(b)); return d;
}
__device__ __forceinline__ float ex2a(float x) {
    float r; asm("ex2.approx.f32 %0, %1;" : "=f"(r) : "f"(x)); return r;
}
__device__ __forceinline__ float rcpa(float x) {
    float r; asm("rcp.approx.f32 %0, %1;" : "=f"(r) : "f"(x)); return r;
}
__device__ __forceinline__ float sig_f(float v) {
    return rcpa(1.0f + ex2a(v * -1.442695041f));
}
__device__ __forceinline__ float tanh_f(float v) {
    return fmaf(2.0f, rcpa(1.0f + ex2a(v * -2.885390082f)), -1.0f);
}

// Cohort = 4 lanes <-> 3 sequences. Lane q owns gate rows {r,z,n} x units
// [6q, 6q+6) and computes FULL k=24 matvec for the cohort's 3 seqs.
// NSEQ=3 balances the L1-crossbar floor (x4/3 vs NSEQ=4) against warp count
// (1366 warps = 2.31/SMSP) to minimize latency-exposure x floor.
__global__ void __launch_bounds__(TPB, 10)
trendgru_kernel(const float* __restrict__ x,
                const float* __restrict__ W_ih,
                const float* __restrict__ b_ih,
                const float* __restrict__ W_hh,
                const float* __restrict__ b_hh,
                const float* __restrict__ fc_w,
                const float* __restrict__ fc_b,
                float* __restrict__ out,
                int B, int T)
{
    // sW[q*218 + j*24 + k] = pack2(W_hh[r0][k], W_hh[r0+1][k]),
    //  j = gate*3+p (gate 0=r,1=z,2=n), r0 = gate*24 + 6q + 2p, k = 0..23
    __shared__ __align__(16) u64 sW[4 * WSTRIDE];
    __shared__ __align__(16) ulonglong2 cRZ[4][6];  // (W_ih pair, b_ih+b_hh pair)
    __shared__ __align__(16) ulonglong2 cN[4][3];   // (W_ih_n pair, b_ih_n pair)
    __shared__ u64 cNH[4][3];                       // b_hh n pairs

    const int tid = threadIdx.x;
    for (int i = tid; i < 4 * 216; i += TPB) {
        int qq = i / 216, rem = i % 216;
        int j = rem / 24, k = rem % 24;
        int gate = j / 3, p = j % 3;
        int r0 = gate * 24 + 6 * qq + 2 * p;
        sW[qq * WSTRIDE + j * 24 + k] = pack2(W_hh[r0 * HID + k], W_hh[(r0 + 1) * HID + k]);
    }
    if (tid < 24) {
        int qq = tid / 6, j6 = tid % 6;
        int gate = j6 / 3, p = j6 % 3;
        int r0 = gate * 24 + 6 * qq + 2 * p;
        cRZ[qq][j6].x = pack2(W_ih[r0], W_ih[r0 + 1]);
        cRZ[qq][j6].y = pack2(b_ih[r0] + b_hh[r0], b_ih[r0 + 1] + b_hh[r0 + 1]);
    }
    if (tid < 12) {
        int qq = tid / 3, p = tid % 3;
        int r0 = 48 + 6 * qq + 2 * p;
        cN[qq][p].x = pack2(W_ih[r0], W_ih[r0 + 1]);
        cN[qq][p].y = pack2(b_ih[r0], b_ih[r0 + 1]);
        cNH[qq][p]  = pack2(b_hh[r0], b_hh[r0 + 1]);
    }
    __syncthreads();

    const int q     = tid & 3;
    const int cbase = tid & ~3;
    const int sbase = ((blockIdx.x << 3) + (tid >> 2)) * NSEQ;   // 8 cohorts/CTA

    const ulonglong2* wq = reinterpret_cast<const ulonglong2*>(&sW[q * WSTRIDE]);

    // per-m clamped sequence index (tail CTA duplicates last seq; store guarded)
    const float* xr[NSEQ];
    #pragma unroll
    for (int m = 0; m < NSEQ; m++) {
        int s = sbase + m;
        if (s > B - 1) s = B - 1;
        xr[m] = x + (size_t)s * T;
    }

    u64 hown[NSEQ][3];   // own h pairs (units 6q..6q+5)
    #pragma unroll
    for (int m = 0; m < NSEQ; m++)
        #pragma unroll
        for (int p = 0; p < 3; p++) hown[m][p] = 0ULL;

    const u64 SGN2 = 0x8000000080000000ULL;

    float xv[NSEQ];
    #pragma unroll
    for (int m = 0; m < NSEQ; m++) xv[m] = __ldg(xr[m]);

    for (int t = 0; t < T; t++) {
        const int tn = (t + 1 < T) ? (t + 1) : t;
        float xnx[NSEQ];
        #pragma unroll
        for (int m = 0; m < NSEQ; m++) xnx[m] = __ldg(xr[m] + tn);

        u64 x2[NSEQ];
        #pragma unroll
        for (int m = 0; m < NSEQ; m++) x2[m] = pack2(xv[m], xv[m]);

        u64 acc[NSEQ][9];
        #pragma unroll
        for (int j6 = 0; j6 < 6; j6++) {          // r (0-2), z (3-5): fold x-proj + biases
            const ulonglong2 w = cRZ[q][j6];
            #pragma unroll
            for (int m = 0; m < NSEQ; m++)
                acc[m][j6] = ffma2(w.x, x2[m], w.y);
        }
        #pragma unroll
        for (int p = 0; p < 3; p++) {             // hn: start from b_hh
            const u64 bv = cNH[q][p];
            #pragma unroll
            for (int m = 0; m < NSEQ; m++) acc[m][6 + p] = bv;
        }

        // matvec over 12 global h-pairs; pair i owned by lane cbase + i/3
        #pragma unroll
        for (int i = 0; i < 12; i++) {
            const int src = cbase + (i / 3);
            u64 e0[NSEQ], e1[NSEQ];
            #pragma unroll
            for (int m = 0; m < NSEQ; m++) {
                const u64 hv = __shfl_sync(0xFFFFFFFFu, hown[m][i % 3], src);
                float h0, h1; unpack2(hv, h0, h1);
                e0[m] = pack2(h0, h0);
                e1[m] = pack2(h1, h1);
            }
            #pragma unroll
            for (int j = 0; j < 9; j++) {
                const ulonglong2 w = wq[j * 12 + i];   // k = 2i (x), 2i+1 (y)
                #pragma unroll
                for (int m = 0; m < NSEQ; m++) {
                    acc[m][j] = ffma2(w.x, e0[m], acc[m][j]);
                    acc[m][j] = ffma2(w.y, e1[m], acc[m][j]);
                }
            }
        }

        // gates + h update: own 3 pairs x NSEQ seqs
        #pragma unroll
        for (int m = 0; m < NSEQ; m++) {
            #pragma unroll
            for (int p = 0; p < 3; p++) {
                float a0, a1, c0, c1;
                unpack2(acc[m][p], a0, a1);
                unpack2(acc[m][3 + p], c0, c1);
                const u64 r2 = pack2(sig_f(a0), sig_f(a1));
                const u64 z2 = pack2(sig_f(c0), sig_f(c1));
                const ulonglong2 wn = cN[q][p];
                const u64 xn = ffma2(wn.x, x2[m], wn.y);
                const u64 npre = ffma2(r2, acc[m][6 + p], xn);
                float n0, n1; unpack2(npre, n0, n1);
                const u64 n2 = pack2(tanh_f(n0), tanh_f(n1));
                // h = n + z*(h - n)
                hown[m][p] = ffma2(z2, fadd2(hown[m][p], n2 ^ SGN2), n2);
            }
        }

        #pragma unroll
        for (int m = 0; m < NSEQ; m++) xv[m] = xnx[m];
    }

    // final fc: partials over own 6 units, reduce across the 4 cohort lanes
    float p0[NSEQ], p1[NSEQ];
    #pragma unroll
    for (int m = 0; m < NSEQ; m++) { p0[m] = 0.f; p1[m] = 0.f; }
    #pragma unroll
    for (int p = 0; p < 3; p++) {
        const int k = 6 * q + 2 * p;
        const float w00 = __ldg(fc_w + k),      w01 = __ldg(fc_w + k + 1);
        const float w10 = __ldg(fc_w + 24 + k), w11 = __ldg(fc_w + 24 + k + 1);
        #pragma unroll
        for (int m = 0; m < NSEQ; m++) {
            float e0, e1; unpack2(hown[m][p], e0, e1);
            p0[m] += w00 * e0 + w01 * e1;
            p1[m] += w10 * e0 + w11 * e1;
        }
    }
    #pragma unroll
    for (int off = 1; off < 4; off <<= 1) {
        #pragma unroll
        for (int m = 0; m < NSEQ; m++) {
            p0[m] += __shfl_xor_sync(0xFFFFFFFFu, p0[m], off);
            p1[m] += __shfl_xor_sync(0xFFFFFFFFu, p1[m], off);
        }
    }
    if (q == 0) {
        const float fb0 = __ldg(fc_b + 0), fb1 = __ldg(fc_b + 1);
        #pragma unroll
        for (int m = 0; m < NSEQ; m++) {
            if (sbase + m < B) {
                out[2 * (sbase + m) + 0] = p0[m] + fb0;
                out[2 * (sbase + m) + 1] = p1[m] + fb1;
            }
        }
    }
}

extern "C" void kernel_launch(void* const* d_in, const int* in_sizes, int n_in,
                              void* d_out, int out_size)
{
    const float* x    = (const float*)d_in[0];
    const float* W_ih = (const float*)d_in[1];
    const float* b_ih = (const float*)d_in[2];
    const float* W_hh = (const float*)d_in[3];
    const float* b_hh = (const float*)d_in[4];
    const float* fc_w = (const float*)d_in[5];
    const float* fc_b = (const float*)d_in[6];
    float* out = (float*)d_out;

    const int B = out_size / 2;
    const int T = in_sizes[0] / B;

    const int seqs_per_cta = 8 * NSEQ;                     // 8 cohorts x NSEQ
    const int grid = (B + seqs_per_cta - 1) / seqs_per_cta;
    trendgru_kernel<<<grid, TPB>>>(x, W_ih, b_ih, W_hh, b_hh, fc_w, fc_b, out, B, T);
}

// round 17
// speedup vs baseline: 2.0225x; 2.0225x over previous
#include <cuda_runtime.h>
#include <cstdint>

#define TPB 64
#define HID 24

typedef unsigned long long u64;

__device__ __forceinline__ u64 pack2(float x, float y) {
    u64 r; asm("mov.b64 %0, {%1, %2};" : "=l"(r) : "f"(x), "f"(y)); return r;
}
__device__ __forceinline__ void unpack2(u64 v, float &x, float &y) {
    asm("mov.b64 {%0, %1}, %2;" : "=f"(x), "=f"(y) : "l"(v));
}
__device__ __forceinline__ float ex2a(float x){float r;asm("ex2.approx.f32 %0, %1;":"=f"(r):"f"(x));return r;}
__device__ __forceinline__ float rcpa(float x){float r;asm("rcp.approx.f32 %0, %1;":"=f"(r):"f"(x));return r;}

// pack two f32 as bf16x2: low element -> bits[15:0], high element -> bits[31:16]
__device__ __forceinline__ uint32_t bfpack(float lo_e, float hi_e) {
    uint32_t r;
    asm("cvt.rn.bf16x2.f32 %0, %1, %2;" : "=r"(r) : "f"(hi_e), "f"(lo_e));
    return r;
}
__device__ __forceinline__ float bflo(uint32_t p){ return __uint_as_float(p << 16); }
__device__ __forceinline__ float bfhi(uint32_t p){ return __uint_as_float(p & 0xFFFF0000u); }
// v -> hi (bf16 round) + lo (bf16 of residual)
__device__ __forceinline__ void split2(float v0, float v1, uint32_t &hi, uint32_t &lo) {
    hi = bfpack(v0, v1);
    lo = bfpack(v0 - bflo(hi), v1 - bfhi(hi));
}

#define MMA(c, A0,A1,A2,A3, B0,B1) \
    asm volatile("mma.sync.aligned.m16n8k16.row.col.f32.bf16.bf16.f32 " \
        "{%0,%1,%2,%3}, {%4,%5,%6,%7}, {%8,%9}, {%0,%1,%2,%3};" \
        : "+f"((c)[0]), "+f"((c)[1]), "+f"((c)[2]), "+f"((c)[3]) \
        : "r"(A0), "r"(A1), "r"(A2), "r"(A3), "r"(B0), "r"(B1))

// Warp = 16 seqs. D[16 seqs x 72 gates] = A[16 x 24 h] * B[24 x 72 W_hh^T],
// 9 N-tiles (r 0-2, z 3-5, n 6-8), 2 K-tiles (k 0-15, 16-23+pad).
// D-fragment position of unit u == A-fragment position for next step: no shuffles.
__global__ void __launch_bounds__(TPB, 7)
trendgru_kernel(const float* __restrict__ x,
                const float* __restrict__ W_ih,
                const float* __restrict__ b_ih,
                const float* __restrict__ W_hh,
                const float* __restrict__ b_hh,
                const float* __restrict__ fc_w,
                const float* __restrict__ fc_b,
                float* __restrict__ out,
                int B, int T)
{
    __shared__ __align__(16) uint2    sBloK0[9][32];   // B_lo kt=0 frags per lane
    __shared__ uint32_t               sBloK1[9][32];   // B_lo kt=1 frag (reg1 = 0)
    __shared__ __align__(16) ulonglong2 sRZ[6][4];     // [nt][tid4] {W_ih pair, (b_ih+b_hh) pair}
    __shared__ __align__(16) ulonglong2 sNI[3][4];     // [j][tid4] {W_ih_n pair, b_ih_n pair}
    __shared__ u64 sBN[3][4];                          // [j][tid4] b_hh n pair

    const int tid  = threadIdx.x;
    const int lane = tid & 31;
    const int wid  = tid >> 5;
    const int tid4 = lane & 3;
    const int g4   = lane >> 2;

    if (tid < 24) {
        int nt = tid >> 2, t4 = tid & 3;
        int g0 = 8 * nt + 2 * t4;
        sRZ[nt][t4] = make_ulonglong2(
            pack2(W_ih[g0], W_ih[g0 + 1]),
            pack2(b_ih[g0] + b_hh[g0], b_ih[g0 + 1] + b_hh[g0 + 1]));
    }
    if (tid >= 32 && tid < 44) {
        int v = tid - 32;
        int j = v >> 2, t4 = v & 3;
        int g0 = 48 + 8 * j + 2 * t4;
        sNI[j][t4] = make_ulonglong2(pack2(W_ih[g0], W_ih[g0 + 1]),
                                     pack2(b_ih[g0], b_ih[g0 + 1]));
        sBN[j][t4] = pack2(b_hh[g0], b_hh[g0 + 1]);
    }

    // weight fragments: B[k][n] = W_hh[n][k]; col n = 8nt + g4,
    // kt0 rows k = {2tid4, +1, +8, +9}; kt1 rows k = {16+2tid4, +1} (rest pad 0)
    uint32_t bhi0[9][2], bhi1[9];
    #pragma unroll
    for (int nt = 0; nt < 9; nt++) {
        const int n = 8 * nt + g4;
        const float* wr = W_hh + n * HID;
        uint32_t lo0, lo1, lo2;
        split2(wr[2 * tid4],      wr[2 * tid4 + 1], bhi0[nt][0], lo0);
        split2(wr[2 * tid4 + 8],  wr[2 * tid4 + 9], bhi0[nt][1], lo1);
        split2(wr[16 + 2 * tid4], wr[17 + 2 * tid4], bhi1[nt],   lo2);
        if (wid == 0) {
            sBloK0[nt][lane] = make_uint2(lo0, lo1);
            sBloK1[nt][lane] = lo2;
        }
    }
    __syncthreads();

    const uint32_t ZR = 0u;

    // this warp's sequences: lane handles rows s0 = base+g4, s1 = s0+8
    const int sW = (blockIdx.x * (TPB / 32) + wid) * 16;
    const int s0 = sW + g4, s1 = s0 + 8;
    const float* xr0 = x + (size_t)s0 * T;
    const float* xr1 = x + (size_t)s1 * T;

    float hv[2][6];    // [row][2*nt + col] : units 8nt + 2tid4 + col
    #pragma unroll
    for (int r = 0; r < 2; r++)
        #pragma unroll
        for (int u = 0; u < 6; u++) hv[r][u] = 0.0f;

    float x0 = __ldg(xr0), x1 = __ldg(xr1);
    const float L2E = 1.442695041f;

    for (int t = 0; t < T; t++) {
        const int tn = (t + 1 < T) ? (t + 1) : t;
        const float x0n = __ldg(xr0 + tn);
        const float x1n = __ldg(xr1 + tn);

        // ---- build A fragments (hi/lo) from h
        // k0: reg0=(r0,cols nt0) reg1=(r1,nt0) reg2=(r0,nt1) reg3=(r1,nt1)
        // k1: reg0=(r0,nt2) reg1=(r1,nt2) reg2=reg3=0
        uint32_t ah[6], al[6];
        #pragma unroll
        for (int nt = 0; nt < 3; nt++)
            #pragma unroll
            for (int r = 0; r < 2; r++) {
                const int idx = (nt < 2) ? (2 * nt + r) : (4 + r);
                split2(hv[r][2 * nt], hv[r][2 * nt + 1], ah[idx], al[idx]);
            }

        // ---- init accumulators
        float c[9][4];
        #pragma unroll
        for (int nt = 0; nt < 6; nt++) {
            const ulonglong2 wb = sRZ[nt][tid4];
            float w0, w1, b0, b1;
            unpack2(wb.x, w0, w1);
            unpack2(wb.y, b0, b1);
            c[nt][0] = fmaf(w0, x0, b0);
            c[nt][1] = fmaf(w1, x0, b1);
            c[nt][2] = fmaf(w0, x1, b0);
            c[nt][3] = fmaf(w1, x1, b1);
        }
        float xnv[2][6];
        #pragma unroll
        for (int j = 0; j < 3; j++) {
            const u64 bn = sBN[j][tid4];
            float bn0, bn1;
            unpack2(bn, bn0, bn1);
            c[6 + j][0] = bn0; c[6 + j][1] = bn1;
            c[6 + j][2] = bn0; c[6 + j][3] = bn1;
            const ulonglong2 wb = sNI[j][tid4];
            float w0, w1, b0, b1;
            unpack2(wb.x, w0, w1);
            unpack2(wb.y, b0, b1);
            xnv[0][2 * j]     = fmaf(w0, x0, b0);
            xnv[0][2 * j + 1] = fmaf(w1, x0, b1);
            xnv[1][2 * j]     = fmaf(w0, x1, b0);
            xnv[1][2 * j + 1] = fmaf(w1, x1, b1);
        }

        // ---- 54 MMA: Whi*Ahi + Whi*Alo + Wlo*Ahi
        #pragma unroll
        for (int nt = 0; nt < 9; nt++) {
            const uint2 bl0 = sBloK0[nt][lane];
            const uint32_t bl1 = sBloK1[nt][lane];
            MMA(c[nt], ah[0], ah[1], ah[2], ah[3], bhi0[nt][0], bhi0[nt][1]);
            MMA(c[nt], ah[4], ah[5], ZR, ZR,       bhi1[nt],    ZR);
            MMA(c[nt], al[0], al[1], al[2], al[3], bhi0[nt][0], bhi0[nt][1]);
            MMA(c[nt], al[4], al[5], ZR, ZR,       bhi1[nt],    ZR);
            MMA(c[nt], ah[0], ah[1], ah[2], ah[3], bl0.x, bl0.y);
            MMA(c[nt], ah[4], ah[5], ZR, ZR,       bl1,   ZR);
        }

        // ---- gates (quad-shared rcp) + h update
        #pragma unroll
        for (int nt = 0; nt < 3; nt++)
            #pragma unroll
            for (int r = 0; r < 2; r++) {
                const float pr0 = c[nt][2 * r],     pr1 = c[nt][2 * r + 1];
                const float pz0 = c[nt + 3][2 * r], pz1 = c[nt + 3][2 * r + 1];
                const float A  = 1.0f + ex2a(pr0 * -L2E);
                const float Bv = 1.0f + ex2a(pr1 * -L2E);
                const float C  = 1.0f + ex2a(pz0 * -L2E);
                const float D  = 1.0f + ex2a(pz1 * -L2E);
                const float AB = A * Bv, CD = C * D;
                const float R  = rcpa(AB * CD);
                const float tC = R * CD, tA = R * AB;
                const float r0 = tC * Bv, r1 = tC * A;
                const float z0 = tA * D,  z1 = tA * C;

                const float an0 = fmaf(r0, c[nt + 6][2 * r],     xnv[r][2 * nt]);
                const float an1 = fmaf(r1, c[nt + 6][2 * r + 1], xnv[r][2 * nt + 1]);
                const float g0 = 1.0f + ex2a(an0 * (-2.0f * L2E));
                const float g1 = 1.0f + ex2a(an1 * (-2.0f * L2E));
                const float rq = rcpa(g0 * g1);
                const float n0 = fmaf(2.0f * rq, g1, -1.0f);
                const float n1 = fmaf(2.0f * rq, g0, -1.0f);

                hv[r][2 * nt]     = fmaf(z0, hv[r][2 * nt]     - n0, n0);
                hv[r][2 * nt + 1] = fmaf(z1, hv[r][2 * nt + 1] - n1, n1);
            }

        x0 = x0n;
        x1 = x1n;
    }

    // ---- final fc: partial over own 6 units (per row), reduce over tid4 group
    float p00 = 0.f, p01 = 0.f, p10 = 0.f, p11 = 0.f;
    #pragma unroll
    for (int nt = 0; nt < 3; nt++)
        #pragma unroll
        for (int col = 0; col < 2; col++) {
            const int u = 8 * nt + 2 * tid4 + col;
            const float w0 = __ldg(fc_w + u);
            const float w1 = __ldg(fc_w + 24 + u);
            p00 += w0 * hv[0][2 * nt + col];
            p01 += w1 * hv[0][2 * nt + col];
            p10 += w0 * hv[1][2 * nt + col];
            p11 += w1 * hv[1][2 * nt + col];
        }
    #pragma unroll
    for (int off = 1; off < 4; off <<= 1) {
        p00 += __shfl_xor_sync(0xFFFFFFFFu, p00, off);
        p01 += __shfl_xor_sync(0xFFFFFFFFu, p01, off);
        p10 += __shfl_xor_sync(0xFFFFFFFFu, p10, off);
        p11 += __shfl_xor_sync(0xFFFFFFFFu, p11, off);
    }
    if (tid4 == 0) {
        const float fb0 = __ldg(fc_b + 0), fb1 = __ldg(fc_b + 1);
        out[2 * s0 + 0] = p00 + fb0;
        out[2 * s0 + 1] = p01 + fb1;
        out[2 * s1 + 0] = p10 + fb0;
        out[2 * s1 + 1] = p11 + fb1;
    }
}

extern "C" void kernel_launch(void* const* d_in, const int* in_sizes, int n_in,
                              void* d_out, int out_size)
{
    const float* x    = (const float*)d_in[0];
    const float* W_ih = (const float*)d_in[1];
    const float* b_ih = (const float*)d_in[2];
    const float* W_hh = (const float*)d_in[3];
    const float* b_hh = (const float*)d_in[4];
    const float* fc_w = (const float*)d_in[5];
    const float* fc_b = (const float*)d_in[6];
    float* out = (float*)d_out;

    const int B = out_size / 2;
    const int T = in_sizes[0] / B;

    const int seqs_per_cta = 16 * (TPB / 32);   // 16 per warp
    const int grid = B / seqs_per_cta;
    trendgru_kernel<<<grid, TPB>>>(x, W_ih, b_ih, W_hh, b_hh, fc_w, fc_b, out, B, T);
}